// round 4
// baseline (speedup 1.0000x reference)
#include <cuda_runtime.h>
#include <cstdint>

#define BB     16
#define TT     2048
#define HH     512
#define CHUNKS 32
#define LL     (TT / CHUNKS)          // 64
#define NTOT   (BB * TT * HH)         // 16777216

#define K_SLOPE  10.0f
#define MAX_PROB 0.8f

// scratch: per-chunk end values E[b][c][h]
__device__ float g_E[BB * CHUNKS * HH];

__device__ __forceinline__ float clamp01(float v) {
    return fminf(fmaxf(v, 0.0f), 1.0f);
}

__device__ __forceinline__ void tf_mix(uint32_t& x0, uint32_t& x1, int r) {
    x0 += x1;
    x1 = __funnelshift_l(x1, x1, r);   // rotl32
    x1 ^= x0;
}

// JAX threefry2x32 (20 rounds), returns o0 ^ o1 (partitionable 32-bit path)
__device__ __forceinline__ uint32_t threefry_xor(uint32_t ks0, uint32_t ks1, uint32_t ks2,
                                                 uint32_t c0, uint32_t c1) {
    uint32_t x0 = c0 + ks0, x1 = c1 + ks1;
    tf_mix(x0, x1, 13); tf_mix(x0, x1, 15); tf_mix(x0, x1, 26); tf_mix(x0, x1, 6);
    x0 += ks1; x1 += ks2 + 1u;
    tf_mix(x0, x1, 17); tf_mix(x0, x1, 29); tf_mix(x0, x1, 16); tf_mix(x0, x1, 24);
    x0 += ks2; x1 += ks0 + 2u;
    tf_mix(x0, x1, 13); tf_mix(x0, x1, 15); tf_mix(x0, x1, 26); tf_mix(x0, x1, 6);
    x0 += ks0; x1 += ks1 + 3u;
    tf_mix(x0, x1, 17); tf_mix(x0, x1, 29); tf_mix(x0, x1, 16); tf_mix(x0, x1, 24);
    x0 += ks1; x1 += ks2 + 4u;
    tf_mix(x0, x1, 13); tf_mix(x0, x1, 15); tf_mix(x0, x1, 26); tf_mix(x0, x1, 6);
    x0 += ks2; x1 += ks0 + 5u;
    return x0 ^ x1;
}

__device__ __forceinline__ float bits_to_uniform(uint32_t bits) {
    return __uint_as_float((bits >> 9) | 0x3f800000u) - 1.0f;
}

// ---------------------------------------------------------------------------
// K1: per-chunk end values with zero initial condition.
// thread idx -> (b, c, h), h fastest (coalesced).
// ---------------------------------------------------------------------------
__global__ void k_chunk_end(const float* __restrict__ x,
                            const float* __restrict__ beta_p) {
    int idx = blockIdx.x * blockDim.x + threadIdx.x;   // 0 .. B*CHUNKS*H-1
    float b  = clamp01(beta_p[0]);
    float om = 1.0f - b;

    int h  = idx & (HH - 1);
    int bc = idx >> 9;            // / HH
    int c  = bc & (CHUNKS - 1);
    int bi = bc >> 5;             // / CHUNKS

    const float* xp = x + ((size_t)(bi * TT + c * LL) * HH + h);
    float acc = 0.0f;
#pragma unroll 8
    for (int i = 0; i < LL; i++) {
        acc = fmaf(b, acc, om * xp[(size_t)i * HH]);
    }
    g_E[idx] = acc;
}

// ---------------------------------------------------------------------------
// K3: main pass. Each thread owns (b, c, h-pair): rebuilds carry from E,
// re-scans its chunk, and does fused sigmoid + partitionable-threefry
// bernoulli. 2 h-lanes per thread (float2) for coalescing + RNG ILP.
// ---------------------------------------------------------------------------
__global__ void k_main(const float* __restrict__ x,
                       const float* __restrict__ beta_p,
                       const int*   __restrict__ seed_p,
                       float* __restrict__ out) {
    int idx = blockIdx.x * blockDim.x + threadIdx.x;   // 0 .. B*CHUNKS*(H/2)-1
    float b  = clamp01(beta_p[0]);
    float om = 1.0f - b;

    // b^LL via squaring (LL = 64 = 2^6)
    float bL = b;
#pragma unroll
    for (int s = 0; s < 6; s++) bL *= bL;

    int hp = idx & (HH / 2 - 1);      // h-pair index, h = 2*hp
    int bc = idx >> 8;                // / (HH/2)
    int c  = bc & (CHUNKS - 1);
    int bi = bc >> 5;                 // batch 0..15

    int h = hp * 2;

    // carry-in = V at end of chunk c-1, rebuilt from E (L2-hot, 1MB total)
    float v0 = 0.0f, v1 = 0.0f;
    const float2* E2 = (const float2*)g_E;
    for (int j = 0; j < c; j++) {
        float2 e = E2[((bi * CHUNKS + j) * HH + h) >> 1];
        v0 = fmaf(bL, v0, e.x);
        v1 = fmaf(bL, v1, e.y);
    }

    // threefry key schedule: key = (0, seed)
    uint32_t ks0 = 0u;
    uint32_t ks1 = (uint32_t)seed_p[0];
    uint32_t ks2 = ks0 ^ ks1 ^ 0x1BD11BDAu;

    uint32_t base = (uint32_t)((bi * TT + c * LL) * HH + h);  // flat elem idx
    const float2* xp = (const float2*)(x + base);
    float2* spikes = (float2*)(out + base);
    float2* vout   = (float2*)(out + NTOT + base);

#pragma unroll 4
    for (int i = 0; i < LL; i++) {
        float2 xv = xp[(size_t)i * (HH / 2)];
        v0 = fmaf(b, v0, om * xv.x);
        v1 = fmaf(b, v1, om * xv.y);

        float z0 = fmaf(K_SLOPE, v0, -K_SLOPE);   // 10*(V-1)
        float z1 = fmaf(K_SLOPE, v1, -K_SLOPE);
        float p0 = __fdividef(MAX_PROB, 1.0f + __expf(-z0));
        float p1 = __fdividef(MAX_PROB, 1.0f + __expf(-z1));

        uint32_t j0 = base + (uint32_t)i * HH;    // element flat index (hi word = 0)
        uint32_t r0 = threefry_xor(ks0, ks1, ks2, 0u, j0);
        uint32_t r1 = threefry_xor(ks0, ks1, ks2, 0u, j0 + 1u);
        float u0 = bits_to_uniform(r0);
        float u1 = bits_to_uniform(r1);

        float2 s, vv;
        s.x = (u0 < p0) ? 1.0f : 0.0f;
        s.y = (u1 < p1) ? 1.0f : 0.0f;
        vv.x = v0; vv.y = v1;
        spikes[(size_t)i * (HH / 2)] = s;
        vout[(size_t)i * (HH / 2)]   = vv;
    }
}

extern "C" void kernel_launch(void* const* d_in, const int* in_sizes, int n_in,
                              void* d_out, int out_size) {
    const float* x    = (const float*)d_in[0];
    const float* beta = (const float*)d_in[1];
    const int*   seed = (const int*)d_in[2];
    float*       out  = (float*)d_out;

    (void)in_sizes; (void)n_in; (void)out_size;

    // K1: B*CHUNKS*H = 262144 threads
    k_chunk_end<<<(BB * CHUNKS * HH) / 256, 256>>>(x, beta);
    // K3: B*CHUNKS*H/2 = 131072 threads (2 h-lanes each)
    k_main<<<(BB * CHUNKS * (HH / 2)) / 256, 256>>>(x, beta, seed, out);
}